// round 13
// baseline (speedup 1.0000x reference)
#include <cuda_runtime.h>
#include <cuda_fp16.h>

#define IN_DIM 256
#define OUT_DIM 128
#define MAX_NODES 100000
#define MAX_EDGES 3200000

// Scratch (device globals = allowed scratch).
__device__ __half g_h[(size_t)MAX_NODES * OUT_DIM];   // 25.6 MB fp16 h
__device__ int    g_deg[MAX_NODES];                   // per-dst edge count
__device__ int    g_off[MAX_NODES];                   // CSR start offsets
__device__ int    g_cur[MAX_NODES];                   // fill cursors
__device__ int2   g_sv[MAX_EDGES];                    // fused (src, val_bits)

// ---- packed dual-fp32 helpers (Blackwell FFMA2; PTX-only path) -------------
__device__ __forceinline__ unsigned long long pack2(float lo, float hi) {
    unsigned long long r;
    asm("mov.b64 %0, {%1, %2};" : "=l"(r) : "f"(lo), "f"(hi));
    return r;
}
__device__ __forceinline__ void unpack2(unsigned long long p, float& lo, float& hi) {
    asm("mov.b64 {%0, %1}, %2;" : "=f"(lo), "=f"(hi) : "l"(p));
}
__device__ __forceinline__ void fma2(unsigned long long& acc,
                                     unsigned long long a, unsigned long long b) {
    asm("fma.rn.f32x2 %0, %1, %2, %0;" : "+l"(acc) : "l"(a), "l"(b));
}

// ---------------------------------------------------------------------------
// Kernel 1: tiled fp32 GEMM  h[M,128] = X[M,256] @ W[256,128]  (fp16 out)
// ---------------------------------------------------------------------------
__global__ __launch_bounds__(256, 2) void gemm_kernel(const float* __restrict__ X,
                                                      const float* __restrict__ W,
                                                      int M) {
    __shared__ float As[2][16][128];
    __shared__ float Bs[2][16][128];

    const int tid = threadIdx.x;
    const int tx = tid & 15;
    const int ty = tid >> 4;
    const int rowBase = blockIdx.x * 128;

    const int ar0 = tid >> 2;
    const int ar1 = (tid + 256) >> 2;
    const int ac  = (tid & 3) * 4;
    const int br0 = tid >> 5;
    const int br1 = (tid + 256) >> 5;
    const int bc  = (tid & 31) * 4;

    const bool aok0 = (rowBase + ar0) < M;
    const bool aok1 = (rowBase + ar1) < M;
    const float* Xp0 = X + (size_t)(rowBase + ar0) * IN_DIM + ac;
    const float* Xp1 = X + (size_t)(rowBase + ar1) * IN_DIM + ac;
    const float* Wp0 = W + (size_t)br0 * OUT_DIM + bc;
    const float* Wp1 = W + (size_t)br1 * OUT_DIM + bc;

    unsigned long long acc2[8][4];
    #pragma unroll
    for (int i = 0; i < 8; i++)
        #pragma unroll
        for (int j = 0; j < 4; j++) acc2[i][j] = 0ull;

    float4 a0, a1, b0, b1;

    a0 = aok0 ? *(const float4*)(Xp0) : make_float4(0.f, 0.f, 0.f, 0.f);
    a1 = aok1 ? *(const float4*)(Xp1) : make_float4(0.f, 0.f, 0.f, 0.f);
    b0 = *(const float4*)(Wp0);
    b1 = *(const float4*)(Wp1);

    As[0][ac + 0][ar0] = a0.x; As[0][ac + 1][ar0] = a0.y;
    As[0][ac + 2][ar0] = a0.z; As[0][ac + 3][ar0] = a0.w;
    As[0][ac + 0][ar1] = a1.x; As[0][ac + 1][ar1] = a1.y;
    As[0][ac + 2][ar1] = a1.z; As[0][ac + 3][ar1] = a1.w;
    *(float4*)(&Bs[0][br0][bc]) = b0;
    *(float4*)(&Bs[0][br1][bc]) = b1;
    __syncthreads();

    const int NT = IN_DIM / 16;
    #pragma unroll 1
    for (int t = 0; t < NT; t++) {
        const int buf = t & 1;

        if (t + 1 < NT) {
            const int koff = (t + 1) * 16;
            a0 = aok0 ? *(const float4*)(Xp0 + koff) : make_float4(0.f, 0.f, 0.f, 0.f);
            a1 = aok1 ? *(const float4*)(Xp1 + koff) : make_float4(0.f, 0.f, 0.f, 0.f);
            b0 = *(const float4*)(Wp0 + (size_t)koff * OUT_DIM);
            b1 = *(const float4*)(Wp1 + (size_t)koff * OUT_DIM);
        }

        #pragma unroll
        for (int k = 0; k < 16; k++) {
            float ra[8], rb[8];
            #pragma unroll
            for (int i = 0; i < 8; i += 4)
                *(float4*)(&ra[i]) = *(const float4*)(&As[buf][k][ty * 8 + i]);
            *(float4*)(&rb[0]) = *(const float4*)(&Bs[buf][k][tx * 4]);
            *(float4*)(&rb[4]) = *(const float4*)(&Bs[buf][k][64 + tx * 4]);

            unsigned long long rbp[4], rap[8];
            #pragma unroll
            for (int j = 0; j < 4; j++) rbp[j] = pack2(rb[2 * j], rb[2 * j + 1]);
            #pragma unroll
            for (int i = 0; i < 8; i++) rap[i] = pack2(ra[i], ra[i]);

            #pragma unroll
            for (int i = 0; i < 8; i++)
                #pragma unroll
                for (int j = 0; j < 4; j++)
                    fma2(acc2[i][j], rap[i], rbp[j]);
        }

        if (t + 1 < NT) {
            const int nb = buf ^ 1;
            As[nb][ac + 0][ar0] = a0.x; As[nb][ac + 1][ar0] = a0.y;
            As[nb][ac + 2][ar0] = a0.z; As[nb][ac + 3][ar0] = a0.w;
            As[nb][ac + 0][ar1] = a1.x; As[nb][ac + 1][ar1] = a1.y;
            As[nb][ac + 2][ar1] = a1.z; As[nb][ac + 3][ar1] = a1.w;
            *(float4*)(&Bs[nb][br0][bc]) = b0;
            *(float4*)(&Bs[nb][br1][bc]) = b1;
            __syncthreads();
        }
    }

    #pragma unroll
    for (int i = 0; i < 8; i++) {
        int gr = rowBase + ty * 8 + i;
        if (gr < M) {
            float4 c0, c1;
            unpack2(acc2[i][0], c0.x, c0.y);
            unpack2(acc2[i][1], c0.z, c0.w);
            unpack2(acc2[i][2], c1.x, c1.y);
            unpack2(acc2[i][3], c1.z, c1.w);
            __half* row = g_h + (size_t)gr * OUT_DIM;
            *(__half2*)(row + tx * 4 + 0)      = __floats2half2_rn(c0.x, c0.y);
            *(__half2*)(row + tx * 4 + 2)      = __floats2half2_rn(c0.z, c0.w);
            *(__half2*)(row + 64 + tx * 4 + 0) = __floats2half2_rn(c1.x, c1.y);
            *(__half2*)(row + 64 + tx * 4 + 2) = __floats2half2_rn(c1.z, c1.w);
        }
    }
}

// ---------------------------------------------------------------------------
// CSR build: zero -> count -> scan -> fill (fused int2 payload)
// ---------------------------------------------------------------------------
__global__ void zero_deg_kernel(int N) {
    int i = blockIdx.x * blockDim.x + threadIdx.x;
    if (i < N) g_deg[i] = 0;
}

__global__ void count_kernel(const int* __restrict__ dst, int E) {
    int i = blockIdx.x * blockDim.x + threadIdx.x;
    if (i < E) atomicAdd(&g_deg[dst[i]], 1);
}

__global__ __launch_bounds__(1024) void scan_kernel(int N) {
    __shared__ int s[1024];
    const int tid = threadIdx.x;
    const int chunk = (N + 1023) / 1024;
    const int lo = tid * chunk;
    const int hi = min(lo + chunk, N);

    int sum = 0;
    for (int i = lo; i < hi; i++) sum += g_deg[i];
    s[tid] = sum;
    __syncthreads();

    #pragma unroll
    for (int d = 1; d < 1024; d <<= 1) {
        int t = (tid >= d) ? s[tid - d] : 0;
        __syncthreads();
        s[tid] += t;
        __syncthreads();
    }
    int run = (tid == 0) ? 0 : s[tid - 1];
    for (int i = lo; i < hi; i++) {
        g_off[i] = run;
        g_cur[i] = run;
        run += g_deg[i];
    }
}

__global__ void fill_kernel(const int* __restrict__ src,
                            const int* __restrict__ dst,
                            const float* __restrict__ vals, int E) {
    int i = blockIdx.x * blockDim.x + threadIdx.x;
    if (i < E) {
        int p = atomicAdd(&g_cur[dst[i]], 1);
        g_sv[p] = make_int2(src[i], __float_as_int(vals[i]));
    }
}

// ---------------------------------------------------------------------------
// Aggregate: one warp per dst node. Lane-cooperative edge staging (coalesced
// int2 loads + shfl distribution), 8-deep gather pipeline, dual accumulator
// sets, fused bias, single non-atomic write.
// ---------------------------------------------------------------------------
__global__ __launch_bounds__(256) void aggregate_kernel(float* __restrict__ out,
                                                        const float* __restrict__ b,
                                                        int N) {
    int node = (int)((blockIdx.x * (long long)blockDim.x + threadIdx.x) >> 5);
    const int lane = threadIdx.x & 31;
    if (node >= N) return;

    const int start = g_off[node];
    const int deg = g_deg[node];

    float4 accA = make_float4(0.f, 0.f, 0.f, 0.f);
    float4 accB = make_float4(0.f, 0.f, 0.f, 0.f);

    const unsigned FULL = 0xffffffffu;
    const __half* __restrict__ hbase = g_h;

    for (int chunk = 0; chunk < deg; chunk += 32) {
        const int n = min(32, deg - chunk);
        // One coalesced load: lane l stages edge chunk+l.
        int2 ed = (lane < n) ? g_sv[start + chunk + lane] : make_int2(0, 0);

        int j = 0;
        for (; j + 7 < n; j += 8) {
            int sidx[8]; float vv[8]; uint2 mm[8];
            #pragma unroll
            for (int q = 0; q < 8; q++) {
                sidx[q] = __shfl_sync(FULL, ed.x, j + q);
                vv[q] = __int_as_float(__shfl_sync(FULL, ed.y, j + q));
            }
            #pragma unroll
            for (int q = 0; q < 8; q++)
                mm[q] = *(const uint2*)(hbase + (size_t)sidx[q] * OUT_DIM + lane * 4);
            #pragma unroll
            for (int q = 0; q < 8; q++) {
                float2 lo = __half22float2(*(const __half2*)&mm[q].x);
                float2 hi = __half22float2(*(const __half2*)&mm[q].y);
                float4& acc = (q & 1) ? accB : accA;
                acc.x += vv[q] * lo.x;
                acc.y += vv[q] * lo.y;
                acc.z += vv[q] * hi.x;
                acc.w += vv[q] * hi.y;
            }
        }
        for (; j < n; j++) {
            int   s0 = __shfl_sync(FULL, ed.x, j);
            float v0 = __int_as_float(__shfl_sync(FULL, ed.y, j));
            uint2 m0 = *(const uint2*)(hbase + (size_t)s0 * OUT_DIM + lane * 4);
            float2 lo = __half22float2(*(const __half2*)&m0.x);
            float2 hi = __half22float2(*(const __half2*)&m0.y);
            accA.x += v0 * lo.x;
            accA.y += v0 * lo.y;
            accA.z += v0 * hi.x;
            accA.w += v0 * hi.y;
        }
    }

    float4 bb = *(const float4*)(b + lane * 4);
    float4 r;
    r.x = accA.x + accB.x + bb.x;
    r.y = accA.y + accB.y + bb.y;
    r.z = accA.z + accB.z + bb.z;
    r.w = accA.w + accB.w + bb.w;
    *(float4*)(out + (size_t)node * OUT_DIM + lane * 4) = r;
}

// ---------------------------------------------------------------------------
// Launch: CSR chain forked onto a second stream, overlapped with GEMM.
// ---------------------------------------------------------------------------
extern "C" void kernel_launch(void* const* d_in, const int* in_sizes, int n_in,
                              void* d_out, int out_size) {
    const float* X     = (const float*)d_in[0];  // feature_map [N, 256]
    const int*   esrc  = (const int*)d_in[1];    // edge_src [E]
    const int*   edst  = (const int*)d_in[2];    // edge_dst [E]
    const float* evals = (const float*)d_in[3];  // edge_vals [E]
    const float* W     = (const float*)d_in[4];  // weights [256, 128]
    const float* b     = (const float*)d_in[5];  // bias [128]
    float* out = (float*)d_out;

    int M = in_sizes[0] / IN_DIM;   // N_NODES
    int E = in_sizes[1];            // N_EDGES
    int eb = (E + 255) / 256;

    static cudaStream_t s2 = []() {
        cudaStream_t s;
        cudaStreamCreateWithFlags(&s, cudaStreamNonBlocking);
        return s;
    }();
    static cudaEvent_t evFork = []() {
        cudaEvent_t e;
        cudaEventCreateWithFlags(&e, cudaEventDisableTiming);
        return e;
    }();
    static cudaEvent_t evJoin = []() {
        cudaEvent_t e;
        cudaEventCreateWithFlags(&e, cudaEventDisableTiming);
        return e;
    }();

    // Fork: CSR build chain on s2, GEMM on the main (capture) stream.
    cudaEventRecord(evFork, 0);
    cudaStreamWaitEvent(s2, evFork, 0);

    zero_deg_kernel<<<(M + 255) / 256, 256, 0, s2>>>(M);
    count_kernel<<<eb, 256, 0, s2>>>(edst, E);
    scan_kernel<<<1, 1024, 0, s2>>>(M);
    fill_kernel<<<eb, 256, 0, s2>>>(esrc, edst, evals, E);
    cudaEventRecord(evJoin, s2);

    gemm_kernel<<<(M + 127) / 128, 256>>>(X, W, M);

    // Join: aggregate needs both CSR and h.
    cudaStreamWaitEvent(0, evJoin, 0);
    long long threads = (long long)M * 32;
    int blocks = (int)((threads + 255) / 256);
    aggregate_kernel<<<blocks, 256>>>(out, b, M);
}

// round 14
// speedup vs baseline: 1.0248x; 1.0248x over previous
#include <cuda_runtime.h>
#include <cuda_fp16.h>

#define IN_DIM 256
#define OUT_DIM 128
#define MAX_NODES 100000
#define MAX_EDGES 3200000

// Scratch (device globals = allowed scratch).
__device__ __half g_h[(size_t)MAX_NODES * OUT_DIM];   // 25.6 MB fp16 h
__device__ int    g_deg[MAX_NODES];                   // per-dst edge count
__device__ int    g_off[MAX_NODES];                   // CSR start offsets
__device__ int    g_cur[MAX_NODES];                   // fill cursors
__device__ int2   g_sv[MAX_EDGES];                    // fused (src, val_bits)

// ---- packed dual-fp32 helpers (Blackwell FFMA2; PTX-only path) -------------
__device__ __forceinline__ unsigned long long pack2(float lo, float hi) {
    unsigned long long r;
    asm("mov.b64 %0, {%1, %2};" : "=l"(r) : "f"(lo), "f"(hi));
    return r;
}
__device__ __forceinline__ void unpack2(unsigned long long p, float& lo, float& hi) {
    asm("mov.b64 {%0, %1}, %2;" : "=f"(lo), "=f"(hi) : "l"(p));
}
__device__ __forceinline__ void fma2(unsigned long long& acc,
                                     unsigned long long a, unsigned long long b) {
    asm("fma.rn.f32x2 %0, %1, %2, %0;" : "+l"(acc) : "l"(a), "l"(b));
}

// ---------------------------------------------------------------------------
// Kernel 1: tiled fp32 GEMM  h[M,128] = X[M,256] @ W[256,128]  (fp16 out)
// ---------------------------------------------------------------------------
__global__ __launch_bounds__(256, 2) void gemm_kernel(const float* __restrict__ X,
                                                      const float* __restrict__ W,
                                                      int M) {
    __shared__ float As[2][16][128];
    __shared__ float Bs[2][16][128];

    const int tid = threadIdx.x;
    const int tx = tid & 15;
    const int ty = tid >> 4;
    const int rowBase = blockIdx.x * 128;

    const int ar0 = tid >> 2;
    const int ar1 = (tid + 256) >> 2;
    const int ac  = (tid & 3) * 4;
    const int br0 = tid >> 5;
    const int br1 = (tid + 256) >> 5;
    const int bc  = (tid & 31) * 4;

    const bool aok0 = (rowBase + ar0) < M;
    const bool aok1 = (rowBase + ar1) < M;
    const float* Xp0 = X + (size_t)(rowBase + ar0) * IN_DIM + ac;
    const float* Xp1 = X + (size_t)(rowBase + ar1) * IN_DIM + ac;
    const float* Wp0 = W + (size_t)br0 * OUT_DIM + bc;
    const float* Wp1 = W + (size_t)br1 * OUT_DIM + bc;

    unsigned long long acc2[8][4];
    #pragma unroll
    for (int i = 0; i < 8; i++)
        #pragma unroll
        for (int j = 0; j < 4; j++) acc2[i][j] = 0ull;

    float4 a0, a1, b0, b1;

    a0 = aok0 ? *(const float4*)(Xp0) : make_float4(0.f, 0.f, 0.f, 0.f);
    a1 = aok1 ? *(const float4*)(Xp1) : make_float4(0.f, 0.f, 0.f, 0.f);
    b0 = *(const float4*)(Wp0);
    b1 = *(const float4*)(Wp1);

    As[0][ac + 0][ar0] = a0.x; As[0][ac + 1][ar0] = a0.y;
    As[0][ac + 2][ar0] = a0.z; As[0][ac + 3][ar0] = a0.w;
    As[0][ac + 0][ar1] = a1.x; As[0][ac + 1][ar1] = a1.y;
    As[0][ac + 2][ar1] = a1.z; As[0][ac + 3][ar1] = a1.w;
    *(float4*)(&Bs[0][br0][bc]) = b0;
    *(float4*)(&Bs[0][br1][bc]) = b1;
    __syncthreads();

    const int NT = IN_DIM / 16;
    #pragma unroll 1
    for (int t = 0; t < NT; t++) {
        const int buf = t & 1;

        if (t + 1 < NT) {
            const int koff = (t + 1) * 16;
            a0 = aok0 ? *(const float4*)(Xp0 + koff) : make_float4(0.f, 0.f, 0.f, 0.f);
            a1 = aok1 ? *(const float4*)(Xp1 + koff) : make_float4(0.f, 0.f, 0.f, 0.f);
            b0 = *(const float4*)(Wp0 + (size_t)koff * OUT_DIM);
            b1 = *(const float4*)(Wp1 + (size_t)koff * OUT_DIM);
        }

        #pragma unroll
        for (int k = 0; k < 16; k++) {
            float ra[8], rb[8];
            #pragma unroll
            for (int i = 0; i < 8; i += 4)
                *(float4*)(&ra[i]) = *(const float4*)(&As[buf][k][ty * 8 + i]);
            *(float4*)(&rb[0]) = *(const float4*)(&Bs[buf][k][tx * 4]);
            *(float4*)(&rb[4]) = *(const float4*)(&Bs[buf][k][64 + tx * 4]);

            unsigned long long rbp[4], rap[8];
            #pragma unroll
            for (int j = 0; j < 4; j++) rbp[j] = pack2(rb[2 * j], rb[2 * j + 1]);
            #pragma unroll
            for (int i = 0; i < 8; i++) rap[i] = pack2(ra[i], ra[i]);

            #pragma unroll
            for (int i = 0; i < 8; i++)
                #pragma unroll
                for (int j = 0; j < 4; j++)
                    fma2(acc2[i][j], rap[i], rbp[j]);
        }

        if (t + 1 < NT) {
            const int nb = buf ^ 1;
            As[nb][ac + 0][ar0] = a0.x; As[nb][ac + 1][ar0] = a0.y;
            As[nb][ac + 2][ar0] = a0.z; As[nb][ac + 3][ar0] = a0.w;
            As[nb][ac + 0][ar1] = a1.x; As[nb][ac + 1][ar1] = a1.y;
            As[nb][ac + 2][ar1] = a1.z; As[nb][ac + 3][ar1] = a1.w;
            *(float4*)(&Bs[nb][br0][bc]) = b0;
            *(float4*)(&Bs[nb][br1][bc]) = b1;
            __syncthreads();
        }
    }

    #pragma unroll
    for (int i = 0; i < 8; i++) {
        int gr = rowBase + ty * 8 + i;
        if (gr < M) {
            float4 c0, c1;
            unpack2(acc2[i][0], c0.x, c0.y);
            unpack2(acc2[i][1], c0.z, c0.w);
            unpack2(acc2[i][2], c1.x, c1.y);
            unpack2(acc2[i][3], c1.z, c1.w);
            __half* row = g_h + (size_t)gr * OUT_DIM;
            *(__half2*)(row + tx * 4 + 0)      = __floats2half2_rn(c0.x, c0.y);
            *(__half2*)(row + tx * 4 + 2)      = __floats2half2_rn(c0.z, c0.w);
            *(__half2*)(row + 64 + tx * 4 + 0) = __floats2half2_rn(c1.x, c1.y);
            *(__half2*)(row + 64 + tx * 4 + 2) = __floats2half2_rn(c1.z, c1.w);
        }
    }
}

// ---------------------------------------------------------------------------
// CSR build: zero -> count -> scan -> fill (fused int2 payload)
// ---------------------------------------------------------------------------
__global__ void zero_deg_kernel(int N) {
    int i = blockIdx.x * blockDim.x + threadIdx.x;
    if (i < N) g_deg[i] = 0;
}

__global__ void count_kernel(const int* __restrict__ dst, int E) {
    int i = blockIdx.x * blockDim.x + threadIdx.x;
    if (i < E) atomicAdd(&g_deg[dst[i]], 1);
}

__global__ __launch_bounds__(1024) void scan_kernel(int N) {
    __shared__ int s[1024];
    const int tid = threadIdx.x;
    const int chunk = (N + 1023) / 1024;
    const int lo = tid * chunk;
    const int hi = min(lo + chunk, N);

    int sum = 0;
    for (int i = lo; i < hi; i++) sum += g_deg[i];
    s[tid] = sum;
    __syncthreads();

    #pragma unroll
    for (int d = 1; d < 1024; d <<= 1) {
        int t = (tid >= d) ? s[tid - d] : 0;
        __syncthreads();
        s[tid] += t;
        __syncthreads();
    }
    int run = (tid == 0) ? 0 : s[tid - 1];
    for (int i = lo; i < hi; i++) {
        g_off[i] = run;
        g_cur[i] = run;
        run += g_deg[i];
    }
}

__global__ void fill_kernel(const int* __restrict__ src,
                            const int* __restrict__ dst,
                            const float* __restrict__ vals, int E) {
    int i = blockIdx.x * blockDim.x + threadIdx.x;
    if (i < E) {
        int p = atomicAdd(&g_cur[dst[i]], 1);
        g_sv[p] = make_int2(src[i], __float_as_int(vals[i]));
    }
}

// ---------------------------------------------------------------------------
// Aggregate v3: one warp per dst node, TWO edges in parallel per iteration.
// Half-warp (16 lanes) covers one 256-B h row via uint4 (8 fp16 cols/lane).
// 1 warp-LDG per edge total (vs 2 before) -> halves the LSU floor and the
// per-warp serial length. Cross-half combine via shfl, fused bias, single
// non-atomic write.
// ---------------------------------------------------------------------------
__global__ __launch_bounds__(256) void aggregate_kernel(float* __restrict__ out,
                                                        const float* __restrict__ b,
                                                        int N) {
    int node = (int)((blockIdx.x * (long long)blockDim.x + threadIdx.x) >> 5);
    const int lane = threadIdx.x & 31;
    if (node >= N) return;

    const int half = lane >> 4;     // 0: even slots, 1: odd slots
    const int hl = lane & 15;       // position within half-warp
    const int start = g_off[node];
    const int end = start + g_deg[node];

    // Lane accumulates cols [hl*8, hl*8+8) as fp32.
    float4 accA0 = make_float4(0.f, 0.f, 0.f, 0.f);
    float4 accA1 = make_float4(0.f, 0.f, 0.f, 0.f);
    float4 accB0 = make_float4(0.f, 0.f, 0.f, 0.f);
    float4 accB1 = make_float4(0.f, 0.f, 0.f, 0.f);

    const __half* __restrict__ hbase = g_h;

    int i = start + half;
    // MLP=2 per half: two edges of this half in flight.
    for (; i + 2 < end; i += 4) {
        int2 eA = __ldg(&g_sv[i]);
        int2 eB = __ldg(&g_sv[i + 2]);
        uint4 mA = *(const uint4*)(hbase + (size_t)eA.x * OUT_DIM + hl * 8);
        uint4 mB = *(const uint4*)(hbase + (size_t)eB.x * OUT_DIM + hl * 8);
        float vA = __int_as_float(eA.y);
        float vB = __int_as_float(eB.y);

        float2 a0 = __half22float2(*(const __half2*)&mA.x);
        float2 a1 = __half22float2(*(const __half2*)&mA.y);
        float2 a2 = __half22float2(*(const __half2*)&mA.z);
        float2 a3 = __half22float2(*(const __half2*)&mA.w);
        accA0.x += vA * a0.x; accA0.y += vA * a0.y;
        accA0.z += vA * a1.x; accA0.w += vA * a1.y;
        accA1.x += vA * a2.x; accA1.y += vA * a2.y;
        accA1.z += vA * a3.x; accA1.w += vA * a3.y;

        float2 b0f = __half22float2(*(const __half2*)&mB.x);
        float2 b1f = __half22float2(*(const __half2*)&mB.y);
        float2 b2f = __half22float2(*(const __half2*)&mB.z);
        float2 b3f = __half22float2(*(const __half2*)&mB.w);
        accB0.x += vB * b0f.x; accB0.y += vB * b0f.y;
        accB0.z += vB * b1f.x; accB0.w += vB * b1f.y;
        accB1.x += vB * b2f.x; accB1.y += vB * b2f.y;
        accB1.z += vB * b3f.x; accB1.w += vB * b3f.y;
    }
    for (; i < end; i += 2) {
        int2 e = __ldg(&g_sv[i]);
        uint4 m = *(const uint4*)(hbase + (size_t)e.x * OUT_DIM + hl * 8);
        float v = __int_as_float(e.y);
        float2 p0 = __half22float2(*(const __half2*)&m.x);
        float2 p1 = __half22float2(*(const __half2*)&m.y);
        float2 p2 = __half22float2(*(const __half2*)&m.z);
        float2 p3 = __half22float2(*(const __half2*)&m.w);
        accA0.x += v * p0.x; accA0.y += v * p0.y;
        accA0.z += v * p1.x; accA0.w += v * p1.y;
        accA1.x += v * p2.x; accA1.y += v * p2.y;
        accA1.z += v * p3.x; accA1.w += v * p3.y;
    }

    // Merge the two accumulator sets.
    float4 r0, r1;
    r0.x = accA0.x + accB0.x; r0.y = accA0.y + accB0.y;
    r0.z = accA0.z + accB0.z; r0.w = accA0.w + accB0.w;
    r1.x = accA1.x + accB1.x; r1.y = accA1.y + accB1.y;
    r1.z = accA1.z + accB1.z; r1.w = accA1.w + accB1.w;

    // Combine halves: lane l (<16) += lane l+16 (same columns, other slots).
    const unsigned FULL = 0xffffffffu;
    r0.x += __shfl_down_sync(FULL, r0.x, 16);
    r0.y += __shfl_down_sync(FULL, r0.y, 16);
    r0.z += __shfl_down_sync(FULL, r0.z, 16);
    r0.w += __shfl_down_sync(FULL, r0.w, 16);
    r1.x += __shfl_down_sync(FULL, r1.x, 16);
    r1.y += __shfl_down_sync(FULL, r1.y, 16);
    r1.z += __shfl_down_sync(FULL, r1.z, 16);
    r1.w += __shfl_down_sync(FULL, r1.w, 16);

    if (half == 0) {
        float4 bb0 = *(const float4*)(b + hl * 8);
        float4 bb1 = *(const float4*)(b + hl * 8 + 4);
        r0.x += bb0.x; r0.y += bb0.y; r0.z += bb0.z; r0.w += bb0.w;
        r1.x += bb1.x; r1.y += bb1.y; r1.z += bb1.z; r1.w += bb1.w;
        float* orow = out + (size_t)node * OUT_DIM + hl * 8;
        *(float4*)(orow + 0) = r0;
        *(float4*)(orow + 4) = r1;
    }
}

// ---------------------------------------------------------------------------
// Launch: CSR chain forked onto a second stream, overlapped with GEMM.
// ---------------------------------------------------------------------------
extern "C" void kernel_launch(void* const* d_in, const int* in_sizes, int n_in,
                              void* d_out, int out_size) {
    const float* X     = (const float*)d_in[0];  // feature_map [N, 256]
    const int*   esrc  = (const int*)d_in[1];    // edge_src [E]
    const int*   edst  = (const int*)d_in[2];    // edge_dst [E]
    const float* evals = (const float*)d_in[3];  // edge_vals [E]
    const float* W     = (const float*)d_in[4];  // weights [256, 128]
    const float* b     = (const float*)d_in[5];  // bias [128]
    float* out = (float*)d_out;

    int M = in_sizes[0] / IN_DIM;   // N_NODES
    int E = in_sizes[1];            // N_EDGES
    int eb = (E + 255) / 256;

    static cudaStream_t s2 = []() {
        cudaStream_t s;
        cudaStreamCreateWithFlags(&s, cudaStreamNonBlocking);
        return s;
    }();
    static cudaEvent_t evFork = []() {
        cudaEvent_t e;
        cudaEventCreateWithFlags(&e, cudaEventDisableTiming);
        return e;
    }();
    static cudaEvent_t evJoin = []() {
        cudaEvent_t e;
        cudaEventCreateWithFlags(&e, cudaEventDisableTiming);
        return e;
    }();

    // Fork: CSR build chain on s2, GEMM on the main (capture) stream.
    cudaEventRecord(evFork, 0);
    cudaStreamWaitEvent(s2, evFork, 0);

    zero_deg_kernel<<<(M + 255) / 256, 256, 0, s2>>>(M);
    count_kernel<<<eb, 256, 0, s2>>>(edst, E);
    scan_kernel<<<1, 1024, 0, s2>>>(M);
    fill_kernel<<<eb, 256, 0, s2>>>(esrc, edst, evals, E);
    cudaEventRecord(evJoin, s2);

    gemm_kernel<<<(M + 127) / 128, 256>>>(X, W, M);

    // Join: aggregate needs both CSR and h.
    cudaStreamWaitEvent(0, evJoin, 0);
    long long threads = (long long)M * 32;
    int blocks = (int)((threads + 255) / 256);
    aggregate_kernel<<<blocks, 256>>>(out, b, M);
}

// round 15
// speedup vs baseline: 1.0613x; 1.0356x over previous
#include <cuda_runtime.h>
#include <cuda_fp16.h>

#define IN_DIM 256
#define OUT_DIM 128
#define MAX_NODES 100000
#define MAX_EDGES 3200000

// Scratch (device globals = allowed scratch).
__device__ __half g_h[(size_t)MAX_NODES * OUT_DIM];   // 25.6 MB fp16 h
__device__ int    g_deg[MAX_NODES];                   // per-dst edge count
__device__ int    g_off[MAX_NODES];                   // CSR start offsets
__device__ int    g_cur[MAX_NODES];                   // fill cursors
__device__ int2   g_sv[MAX_EDGES];                    // fused (src, val_bits)

// ---- packed dual-fp32 helpers (Blackwell FFMA2; PTX-only path) -------------
__device__ __forceinline__ unsigned long long pack2(float lo, float hi) {
    unsigned long long r;
    asm("mov.b64 %0, {%1, %2};" : "=l"(r) : "f"(lo), "f"(hi));
    return r;
}
__device__ __forceinline__ void unpack2(unsigned long long p, float& lo, float& hi) {
    asm("mov.b64 {%0, %1}, %2;" : "=f"(lo), "=f"(hi) : "l"(p));
}
__device__ __forceinline__ void fma2(unsigned long long& acc,
                                     unsigned long long a, unsigned long long b) {
    asm("fma.rn.f32x2 %0, %1, %2, %0;" : "+l"(acc) : "l"(a), "l"(b));
}

// ---------------------------------------------------------------------------
// Kernel 1: tiled fp32 GEMM  h[M,128] = X[M,256] @ W[256,128]  (fp16 out)
// BM=128, BN=128, BK=32 (8 k-tiles, 8 barriers instead of 16), 256 threads,
// 8x8 register tile, FFMA2 inner product, double-buffered dynamic smem.
// ---------------------------------------------------------------------------
__global__ __launch_bounds__(256, 2) void gemm_kernel(const float* __restrict__ X,
                                                      const float* __restrict__ W,
                                                      int M) {
    extern __shared__ float smem[];
    // Layout: As[2][32][128] then Bs[2][32][128]  (k-major As = transposed A)
    float (*As)[32][128] = (float (*)[32][128])(smem);
    float (*Bs)[32][128] = (float (*)[32][128])(smem + 2 * 32 * 128);

    const int tid = threadIdx.x;
    const int tx = tid & 15;
    const int ty = tid >> 4;
    const int rowBase = blockIdx.x * 128;

    // Per-thread load coords: 4 float4 each for A and B per k-tile.
    // A: f = tid + l*256 ; r = f>>3 (0..127) ; c = (f&7)*4 (0..28)
    // B: f = tid + l*256 ; r = f>>5 (0..31)  ; c = (f&31)*4
    int  arL[4]; bool aokL[4];
    const int ac = (tid & 7) * 4;
    const int bc = (tid & 31) * 4;
    int brL[4];
    #pragma unroll
    for (int l = 0; l < 4; l++) {
        int f = tid + l * 256;
        arL[l] = f >> 3;
        brL[l] = f >> 5;
        aokL[l] = (rowBase + arL[l]) < M;
    }

    unsigned long long acc2[8][4];
    #pragma unroll
    for (int i = 0; i < 8; i++)
        #pragma unroll
        for (int j = 0; j < 4; j++) acc2[i][j] = 0ull;

    float4 av[4], bv[4];

    // Prologue: load k-tile 0.
    #pragma unroll
    for (int l = 0; l < 4; l++) {
        av[l] = aokL[l] ? *(const float4*)(X + (size_t)(rowBase + arL[l]) * IN_DIM + ac)
                        : make_float4(0.f, 0.f, 0.f, 0.f);
        bv[l] = *(const float4*)(W + (size_t)brL[l] * OUT_DIM + bc);
    }
    #pragma unroll
    for (int l = 0; l < 4; l++) {
        As[0][ac + 0][arL[l]] = av[l].x;
        As[0][ac + 1][arL[l]] = av[l].y;
        As[0][ac + 2][arL[l]] = av[l].z;
        As[0][ac + 3][arL[l]] = av[l].w;
        *(float4*)(&Bs[0][brL[l]][bc]) = bv[l];
    }
    __syncthreads();

    const int NT = IN_DIM / 32;  // 8 k-tiles
    #pragma unroll 1
    for (int t = 0; t < NT; t++) {
        const int buf = t & 1;

        // Prefetch k-tile t+1 into registers.
        if (t + 1 < NT) {
            const int koff = (t + 1) * 32;
            #pragma unroll
            for (int l = 0; l < 4; l++) {
                av[l] = aokL[l]
                    ? *(const float4*)(X + (size_t)(rowBase + arL[l]) * IN_DIM + koff + ac)
                    : make_float4(0.f, 0.f, 0.f, 0.f);
                bv[l] = *(const float4*)(W + (size_t)(koff + brL[l]) * OUT_DIM + bc);
            }
        }

        // Compute 32 k-steps on current buffer.
        #pragma unroll
        for (int k = 0; k < 32; k++) {
            float ra[8], rb[8];
            #pragma unroll
            for (int i = 0; i < 8; i += 4)
                *(float4*)(&ra[i]) = *(const float4*)(&As[buf][k][ty * 8 + i]);
            *(float4*)(&rb[0]) = *(const float4*)(&Bs[buf][k][tx * 4]);
            *(float4*)(&rb[4]) = *(const float4*)(&Bs[buf][k][64 + tx * 4]);

            unsigned long long rbp[4], rap[8];
            #pragma unroll
            for (int j = 0; j < 4; j++) rbp[j] = pack2(rb[2 * j], rb[2 * j + 1]);
            #pragma unroll
            for (int i = 0; i < 8; i++) rap[i] = pack2(ra[i], ra[i]);

            #pragma unroll
            for (int i = 0; i < 8; i++)
                #pragma unroll
                for (int j = 0; j < 4; j++)
                    fma2(acc2[i][j], rap[i], rbp[j]);
        }

        // Publish k-tile t+1.
        if (t + 1 < NT) {
            const int nb = buf ^ 1;
            #pragma unroll
            for (int l = 0; l < 4; l++) {
                As[nb][ac + 0][arL[l]] = av[l].x;
                As[nb][ac + 1][arL[l]] = av[l].y;
                As[nb][ac + 2][arL[l]] = av[l].z;
                As[nb][ac + 3][arL[l]] = av[l].w;
                *(float4*)(&Bs[nb][brL[l]][bc]) = bv[l];
            }
            __syncthreads();
        }
    }

    #pragma unroll
    for (int i = 0; i < 8; i++) {
        int gr = rowBase + ty * 8 + i;
        if (gr < M) {
            float4 c0, c1;
            unpack2(acc2[i][0], c0.x, c0.y);
            unpack2(acc2[i][1], c0.z, c0.w);
            unpack2(acc2[i][2], c1.x, c1.y);
            unpack2(acc2[i][3], c1.z, c1.w);
            __half* row = g_h + (size_t)gr * OUT_DIM;
            *(__half2*)(row + tx * 4 + 0)      = __floats2half2_rn(c0.x, c0.y);
            *(__half2*)(row + tx * 4 + 2)      = __floats2half2_rn(c0.z, c0.w);
            *(__half2*)(row + 64 + tx * 4 + 0) = __floats2half2_rn(c1.x, c1.y);
            *(__half2*)(row + 64 + tx * 4 + 2) = __floats2half2_rn(c1.z, c1.w);
        }
    }
}

// ---------------------------------------------------------------------------
// CSR build: zero -> count -> scan -> fill (fused int2 payload)
// ---------------------------------------------------------------------------
__global__ void zero_deg_kernel(int N) {
    int i = blockIdx.x * blockDim.x + threadIdx.x;
    if (i < N) g_deg[i] = 0;
}

__global__ void count_kernel(const int* __restrict__ dst, int E) {
    int i = blockIdx.x * blockDim.x + threadIdx.x;
    if (i < E) atomicAdd(&g_deg[dst[i]], 1);
}

__global__ __launch_bounds__(1024) void scan_kernel(int N) {
    __shared__ int s[1024];
    const int tid = threadIdx.x;
    const int chunk = (N + 1023) / 1024;
    const int lo = tid * chunk;
    const int hi = min(lo + chunk, N);

    int sum = 0;
    for (int i = lo; i < hi; i++) sum += g_deg[i];
    s[tid] = sum;
    __syncthreads();

    #pragma unroll
    for (int d = 1; d < 1024; d <<= 1) {
        int t = (tid >= d) ? s[tid - d] : 0;
        __syncthreads();
        s[tid] += t;
        __syncthreads();
    }
    int run = (tid == 0) ? 0 : s[tid - 1];
    for (int i = lo; i < hi; i++) {
        g_off[i] = run;
        g_cur[i] = run;
        run += g_deg[i];
    }
}

__global__ void fill_kernel(const int* __restrict__ src,
                            const int* __restrict__ dst,
                            const float* __restrict__ vals, int E) {
    int i = blockIdx.x * blockDim.x + threadIdx.x;
    if (i < E) {
        int p = atomicAdd(&g_cur[dst[i]], 1);
        g_sv[p] = make_int2(src[i], __float_as_int(vals[i]));
    }
}

// ---------------------------------------------------------------------------
// Aggregate (R10 version — best measured): one warp per dst node, 4-deep
// gather pipeline, fused bias, single non-atomic write.
// ---------------------------------------------------------------------------
__global__ __launch_bounds__(256) void aggregate_kernel(float* __restrict__ out,
                                                        const float* __restrict__ b,
                                                        int N) {
    int node = (int)((blockIdx.x * (long long)blockDim.x + threadIdx.x) >> 5);
    const int lane = threadIdx.x & 31;
    if (node >= N) return;

    const int start = g_off[node];
    const int end = start + g_deg[node];

    float4 acc = make_float4(0.f, 0.f, 0.f, 0.f);

    int i = start;
    for (; i + 3 < end; i += 4) {
        int2 e0 = g_sv[i], e1 = g_sv[i + 1], e2 = g_sv[i + 2], e3 = g_sv[i + 3];
        uint2 m0 = *(const uint2*)(g_h + (size_t)e0.x * OUT_DIM + lane * 4);
        uint2 m1 = *(const uint2*)(g_h + (size_t)e1.x * OUT_DIM + lane * 4);
        uint2 m2 = *(const uint2*)(g_h + (size_t)e2.x * OUT_DIM + lane * 4);
        uint2 m3 = *(const uint2*)(g_h + (size_t)e3.x * OUT_DIM + lane * 4);
        float v0 = __int_as_float(e0.y), v1 = __int_as_float(e1.y);
        float v2 = __int_as_float(e2.y), v3 = __int_as_float(e3.y);
        float2 a0 = __half22float2(*(const __half2*)&m0.x);
        float2 b0f = __half22float2(*(const __half2*)&m0.y);
        float2 a1 = __half22float2(*(const __half2*)&m1.x);
        float2 b1f = __half22float2(*(const __half2*)&m1.y);
        float2 a2 = __half22float2(*(const __half2*)&m2.x);
        float2 b2f = __half22float2(*(const __half2*)&m2.y);
        float2 a3 = __half22float2(*(const __half2*)&m3.x);
        float2 b3f = __half22float2(*(const __half2*)&m3.y);
        acc.x += v0 * a0.x + v1 * a1.x + v2 * a2.x + v3 * a3.x;
        acc.y += v0 * a0.y + v1 * a1.y + v2 * a2.y + v3 * a3.y;
        acc.z += v0 * b0f.x + v1 * b1f.x + v2 * b2f.x + v3 * b3f.x;
        acc.w += v0 * b0f.y + v1 * b1f.y + v2 * b2f.y + v3 * b3f.y;
    }
    for (; i < end; i++) {
        int2 e0 = g_sv[i];
        uint2 m0 = *(const uint2*)(g_h + (size_t)e0.x * OUT_DIM + lane * 4);
        float v0 = __int_as_float(e0.y);
        float2 a0 = __half22float2(*(const __half2*)&m0.x);
        float2 b0f = __half22float2(*(const __half2*)&m0.y);
        acc.x += v0 * a0.x;
        acc.y += v0 * a0.y;
        acc.z += v0 * b0f.x;
        acc.w += v0 * b0f.y;
    }

    float4 bb = *(const float4*)(b + lane * 4);
    acc.x += bb.x; acc.y += bb.y; acc.z += bb.z; acc.w += bb.w;
    *(float4*)(out + (size_t)node * OUT_DIM + lane * 4) = acc;
}

// ---------------------------------------------------------------------------
// Launch: CSR chain forked onto a second stream, overlapped with GEMM.
// ---------------------------------------------------------------------------
extern "C" void kernel_launch(void* const* d_in, const int* in_sizes, int n_in,
                              void* d_out, int out_size) {
    const float* X     = (const float*)d_in[0];  // feature_map [N, 256]
    const int*   esrc  = (const int*)d_in[1];    // edge_src [E]
    const int*   edst  = (const int*)d_in[2];    // edge_dst [E]
    const float* evals = (const float*)d_in[3];  // edge_vals [E]
    const float* W     = (const float*)d_in[4];  // weights [256, 128]
    const float* b     = (const float*)d_in[5];  // bias [128]
    float* out = (float*)d_out;

    int M = in_sizes[0] / IN_DIM;   // N_NODES
    int E = in_sizes[1];            // N_EDGES
    int eb = (E + 255) / 256;

    constexpr int GEMM_SMEM = 2 * 2 * 32 * 128 * (int)sizeof(float);  // 64 KB

    static cudaStream_t s2 = []() {
        cudaStream_t s;
        cudaStreamCreateWithFlags(&s, cudaStreamNonBlocking);
        return s;
    }();
    static cudaEvent_t evFork = []() {
        cudaEvent_t e;
        cudaEventCreateWithFlags(&e, cudaEventDisableTiming);
        return e;
    }();
    static cudaEvent_t evJoin = []() {
        cudaEvent_t e;
        cudaEventCreateWithFlags(&e, cudaEventDisableTiming);
        return e;
    }();
    static bool smemInit = []() {
        cudaFuncSetAttribute(gemm_kernel,
                             cudaFuncAttributeMaxDynamicSharedMemorySize,
                             GEMM_SMEM);
        return true;
    }();
    (void)smemInit;

    // Fork: CSR build chain on s2, GEMM on the main (capture) stream.
    cudaEventRecord(evFork, 0);
    cudaStreamWaitEvent(s2, evFork, 0);

    zero_deg_kernel<<<(M + 255) / 256, 256, 0, s2>>>(M);
    count_kernel<<<eb, 256, 0, s2>>>(edst, E);
    scan_kernel<<<1, 1024, 0, s2>>>(M);
    fill_kernel<<<eb, 256, 0, s2>>>(esrc, edst, evals, E);
    cudaEventRecord(evJoin, s2);

    gemm_kernel<<<(M + 127) / 128, 256, GEMM_SMEM>>>(X, W, M);

    // Join: aggregate needs both CSR and h.
    cudaStreamWaitEvent(0, evJoin, 0);
    long long threads = (long long)M * 32;
    int blocks = (int)((threads + 255) / 256);
    aggregate_kernel<<<blocks, 256>>>(out, b, M);
}